// round 11
// baseline (speedup 1.0000x reference)
#include <cuda_runtime.h>
#include <cuda_fp16.h>
#include <math.h>
#include <stdint.h>

// ===========================================================================
// KnotAttention via mma.sync m16n8k16 fp16 + ldmatrix. Persistent CTAs with a
// cross-tile cp.async software pipeline (1 commit group per GEMM unit).
//  prep_x: x->fp16 (+ index dtype detect)   prep_w: W->[slot][n][k] fp16
//  E: per tile stream: Q, K_0..K_4 -> exp(logits), width-16 partials
//  R: reduce partials -> 1/denominator (softmax over NODE axis)
//  O: per tile stream: V_0..V_4 -> acc += (E*Sinv)*V_r -> direct STG
// ===========================================================================

#define NT       64
#define THREADS  256
#define MAXN     131072
#define MAXTILES (MAXN / NT)
#define SCALE    0.17677669529663687f   // 1/sqrt(32)
#define SH       136                    // smem row stride in halves (272B)
#define ROWB     272
#define A_HALVES (NT * SH)              // 8704
#define W_HALVES (128 * SH)             // 17408
#define SMEM_SZ  ((2 * A_HALVES + 2 * W_HALVES) * 2)   // 104448 B -> 2 CTAs/SM
#define MAXGRID  304

__device__ float  g_E[(size_t)20 * MAXN];
__device__ float  g_part[20 * 16 * MAXTILES];
__device__ float  g_Sinv[20];
__device__ int    g_is64;
__device__ __half g_Wh[11 * 128 * 128];          // [slot][n][k]
__device__ __half g_xh[(size_t)MAXN * 128];      // [n][k]

// -------- helpers --------
__device__ __forceinline__ uint32_t smem_u32(const void* p) {
    uint32_t a;
    asm("{ .reg .u64 t; cvta.to.shared.u64 t, %1; cvt.u32.u64 %0, t; }" : "=r"(a) : "l"(p));
    return a;
}
__device__ __forceinline__ void cpa16(uint32_t s, const void* g) {
    asm volatile("cp.async.cg.shared.global [%0], [%1], 16;" :: "r"(s), "l"(g) : "memory");
}
__device__ __forceinline__ void cpa_commit() { asm volatile("cp.async.commit_group;" ::: "memory"); }
__device__ __forceinline__ void cpa_wait1()  { asm volatile("cp.async.wait_group 1;" ::: "memory"); }

__device__ __forceinline__ void ldsm4(uint32_t& r0, uint32_t& r1, uint32_t& r2,
                                      uint32_t& r3, uint32_t addr) {
    asm volatile("ldmatrix.sync.aligned.m8n8.x4.shared.b16 {%0,%1,%2,%3}, [%4];"
                 : "=r"(r0), "=r"(r1), "=r"(r2), "=r"(r3) : "r"(addr));
}
__device__ __forceinline__ void mma16816(float* c, uint32_t a0, uint32_t a1,
                                         uint32_t a2, uint32_t a3,
                                         uint32_t b0, uint32_t b1) {
    asm volatile(
        "mma.sync.aligned.m16n8k16.row.col.f32.f16.f16.f32 "
        "{%0,%1,%2,%3}, {%4,%5,%6,%7}, {%8,%9}, {%0,%1,%2,%3};"
        : "+f"(c[0]), "+f"(c[1]), "+f"(c[2]), "+f"(c[3])
        : "r"(a0), "r"(a1), "r"(a2), "r"(a3), "r"(b0), "r"(b1));
}

// -------- prep kernels --------
__global__ void knot_prep_x(const float* __restrict__ x,
                            const int* __restrict__ nbr_i32, int total)
{
    if (blockIdx.x == 0 && threadIdx.x == 0) {
        int any = 0;
        #pragma unroll
        for (int i = 1; i < 64; i += 2) any |= nbr_i32[i];
        g_is64 = (any == 0) ? 1 : 0;
    }
    for (int i = blockIdx.x * 256 + threadIdx.x; i < total; i += gridDim.x * 256)
        g_xh[i] = __float2half_rn(x[i]);
}
__global__ void knot_prep_w(const float* __restrict__ wq, const float* __restrict__ wk,
                            const float* __restrict__ wv)
{
    int slot = blockIdx.x;
    __half* dst = g_Wh + slot * 16384;
    for (int i = 0; i < 64; ++i) {
        int f = threadIdx.x + 256 * i;
        int n = f >> 7, d = f & 127;
        int h = n >> 5, k = n & 31;
        float v;
        if (slot == 0)      v = wq[((size_t)h * 128 + d) * 32 + k];
        else if (slot <= 5) v = wk[(((size_t)(h * 5 + (slot - 1)) * 128) + d) * 32 + k];
        else                v = wv[(((size_t)(h * 5 + (slot - 6)) * 128) + d) * 32 + k];
        dst[n * 128 + d] = __float2half_rn(v);
    }
}

// -------- staging --------
__device__ __forceinline__ void stage_A(__half* sA, const void* __restrict__ nbr,
                                        int is64, int n0, int r, int N)
{
    int t = threadIdx.x;
    #pragma unroll
    for (int i = 0; i < 4; ++i) {
        int f = t + 256 * i;               // 64 rows x 16 chunks of 16B
        int row = f >> 4, c16 = f & 15;
        int n = n0 + row;
        int nc = (n < N) ? n : 0;
        long long src;
        if (r == 0) src = nc;
        else {
            long long e = (long long)nc * 4 + (r - 1);
            src = is64 ? __ldg((const long long*)nbr + e)
                       : (long long)__ldg((const int*)nbr + e);
        }
        if (src < 0) src = 0;
        if (src >= N) src = N - 1;
        cpa16(smem_u32(sA + row * SH + c16 * 8), g_xh + ((size_t)src << 7) + c16 * 8);
    }
}
__device__ __forceinline__ void stage_W(__half* sW, int slot)
{
    const __half* src = g_Wh + slot * 16384;
    int t = threadIdx.x;
    #pragma unroll
    for (int i = 0; i < 8; ++i) {
        int f = t + 256 * i;
        int row = f >> 4, c16 = f & 15;
        cpa16(smem_u32(sW + row * SH + c16 * 8), src + row * 128 + c16 * 8);
    }
}

// -------- warp GEMM via ldmatrix: 32(m) x 32(n) per warp --------
__device__ __forceinline__ void gemm64m(uint32_t aAddr, uint32_t bAddr,
                                        float C[2][4][4])
{
    #pragma unroll
    for (int ks = 0; ks < 8; ++ks) {
        uint32_t a0[4], a1[4], b0[4], b1[4];
        ldsm4(a0[0], a0[1], a0[2], a0[3], aAddr + ks * 32);
        ldsm4(a1[0], a1[1], a1[2], a1[3], aAddr + 16 * ROWB + ks * 32);
        ldsm4(b0[0], b0[1], b0[2], b0[3], bAddr + ks * 32);
        ldsm4(b1[0], b1[1], b1[2], b1[3], bAddr + 16 * ROWB + ks * 32);
        mma16816(C[0][0], a0[0], a0[1], a0[2], a0[3], b0[0], b0[1]);
        mma16816(C[0][1], a0[0], a0[1], a0[2], a0[3], b0[2], b0[3]);
        mma16816(C[0][2], a0[0], a0[1], a0[2], a0[3], b1[0], b1[1]);
        mma16816(C[0][3], a0[0], a0[1], a0[2], a0[3], b1[2], b1[3]);
        mma16816(C[1][0], a1[0], a1[1], a1[2], a1[3], b0[0], b0[1]);
        mma16816(C[1][1], a1[0], a1[1], a1[2], a1[3], b0[2], b0[3]);
        mma16816(C[1][2], a1[0], a1[1], a1[2], a1[3], b1[0], b1[1]);
        mma16816(C[1][3], a1[0], a1[1], a1[2], a1[3], b1[2], b1[3]);
    }
}

#define ZERO_C(C)                                                   \
    _Pragma("unroll") for (int mt = 0; mt < 2; ++mt)                \
    _Pragma("unroll") for (int nt = 0; nt < 4; ++nt)                \
    _Pragma("unroll") for (int ci = 0; ci < 4; ++ci) C[mt][nt][ci] = 0.f;

// ======================= kernel E (persistent) =======================
// Units per tile: u=0 Q=(A0,W0); u=1..5 K_{u-1}=(A_{u-1}, W_u).
// A buf parity: (k + (u?u-1:0)) & 1  (k = local tile counter). W buf: g&1.
__global__ __launch_bounds__(THREADS, 2)
void knot_E(const void* __restrict__ nbr, int N, int NBT)
{
    extern __shared__ __align__(16) char smc[];
    __half* sA0 = (__half*)smc;
    __half* sA1 = sA0 + A_HALVES;
    __half* sW0 = sA1 + A_HALVES;
    __half* sW1 = sW0 + W_HALVES;
    __half* sAb[2] = { sA0, sA1 };
    __half* sWb[2] = { sW0, sW1 };

    const int t = threadIdx.x, w = t >> 5, l = t & 31;
    const int wm = w >> 2, wn = w & 3, g8 = l >> 2, t4 = l & 3;
    const int bid = blockIdx.x, grid = gridDim.x;
    const int is64 = g_is64;
    const int h = wn;
    const int K = (NBT - bid + grid - 1) / grid;
    if (K <= 0) return;

    const int j = l >> 3, lr = l & 7;
    const uint32_t aOff = (wm * 32 + (j & 1) * 8 + lr) * ROWB + (j >> 1) * 16;
    const uint32_t bOff = (wn * 32 + (j >> 1) * 8 + lr) * ROWB + (j & 1) * 16;
    const uint32_t aAb[2] = { smem_u32(sA0) + aOff, smem_u32(sA1) + aOff };
    const uint32_t bAb[2] = { smem_u32(sW0) + bOff, smem_u32(sW1) + bOff };

    // prologue: unit0 = {W0, A(tile0, r0)}; unit1 = {W1} (shares A)
    stage_W(sW0, 0); stage_A(sA0, nbr, is64, bid * NT, 0, N); cpa_commit();
    stage_W(sW1, 1); cpa_commit();

    float qC[2][4][4], kC[2][4][4];

    int k = 0, u = 0, tile = bid;
    int k2 = 0, u2 = 2, tile2 = bid;       // cursor for unit g+2
    const int GU = 6 * K;
    for (int g = 0; g < GU; ++g) {
        cpa_wait1();
        __syncthreads();

        const int aPar = (k + (u ? u - 1 : 0)) & 1;
        if (u == 0) { ZERO_C(qC); gemm64m(aAb[aPar], bAb[g & 1], qC); }
        else        { ZERO_C(kC); gemm64m(aAb[aPar], bAb[g & 1], kC); }
        __syncthreads();                   // all reads of this unit's bufs done

        // stage for unit g+2 (cursor k2,u2,tile2), then commit (always)
        if (k2 < K) {
            stage_W(sWb[g & 1], u2);
            if (u2 != 1) {
                int r2 = u2 ? u2 - 1 : 0;
                stage_A(sAb[(k2 + r2) & 1], nbr, is64, tile2 * NT, r2, N);
            }
        }
        cpa_commit();

        // epilogue (u>=1): logits for r = u-1
        if (u >= 1) {
            const int r = u - 1;
            const int n0 = tile * NT;
            float hs = 0.f;
            #pragma unroll
            for (int mt = 0; mt < 2; ++mt) {
                #pragma unroll
                for (int rr2 = 0; rr2 < 2; ++rr2) {
                    int n = n0 + wm * 32 + mt * 16 + g8 + rr2 * 8;
                    float ds = 0.f;
                    #pragma unroll
                    for (int nt = 0; nt < 4; ++nt) {
                        ds = fmaf(qC[mt][nt][rr2 * 2],     kC[mt][nt][rr2 * 2],     ds);
                        ds = fmaf(qC[mt][nt][rr2 * 2 + 1], kC[mt][nt][rr2 * 2 + 1], ds);
                    }
                    ds += __shfl_xor_sync(0xFFFFFFFFu, ds, 1);
                    ds += __shfl_xor_sync(0xFFFFFFFFu, ds, 2);
                    if (t4 == 0) {
                        float e = 0.f;
                        if (n < N) {
                            e = __expf(ds * SCALE);
                            g_E[(size_t)(h * 5 + r) * N + n] = e;
                        }
                        hs += e;
                    }
                }
            }
            // width-16 partials: lanes t4==0 write directly (coalesced 32B)
            if (t4 == 0)
                g_part[(size_t)(h * 5 + r) * (16 * MAXTILES) + tile * 16 + wm * 8 + g8] = hs;
        }

        // advance cursors
        if (++u == 6) { u = 0; ++k; tile += grid; }
        if (++u2 == 6) { u2 = 0; ++k2; tile2 += grid; }
    }
}

// ======================= kernel R =======================
__global__ void knot_R(int cnt)
{
    __shared__ float smr[256];
    const int b = blockIdx.x;
    float s = 0.f;
    for (int i = threadIdx.x; i < cnt; i += 256)
        s += g_part[(size_t)b * (16 * MAXTILES) + i];
    smr[threadIdx.x] = s;
    __syncthreads();
    for (int off = 128; off > 0; off >>= 1) {
        if (threadIdx.x < off) smr[threadIdx.x] += smr[threadIdx.x + off];
        __syncthreads();
    }
    if (threadIdx.x == 0) g_Sinv[b] = 1.0f / smr[0];
}

// ======================= kernel O (persistent) =======================
// Units per tile: u=0..4: V_u = (A_u, W_{6+u}); bufs by global-unit parity.
__global__ __launch_bounds__(THREADS, 2)
void knot_O(const void* __restrict__ nbr, float* __restrict__ out, int N, int NBT)
{
    extern __shared__ __align__(16) char smc[];
    __half* sA0 = (__half*)smc;
    __half* sA1 = sA0 + A_HALVES;
    __half* sW0 = sA1 + A_HALVES;
    __half* sW1 = sW0 + W_HALVES;
    __half* sAb[2] = { sA0, sA1 };
    __half* sWb[2] = { sW0, sW1 };

    const int t = threadIdx.x, w = t >> 5, l = t & 31;
    const int wm = w >> 2, wn = w & 3, g8 = l >> 2, t4 = l & 3;
    const int bid = blockIdx.x, grid = gridDim.x;
    const int is64 = g_is64;
    const int h = wn;
    const int K = (NBT - bid + grid - 1) / grid;
    if (K <= 0) return;

    const int j = l >> 3, lr = l & 7;
    const uint32_t aOff = (wm * 32 + (j & 1) * 8 + lr) * ROWB + (j >> 1) * 16;
    const uint32_t bOff = (wn * 32 + (j >> 1) * 8 + lr) * ROWB + (j & 1) * 16;
    const uint32_t aAb[2] = { smem_u32(sA0) + aOff, smem_u32(sA1) + aOff };
    const uint32_t bAb[2] = { smem_u32(sW0) + bOff, smem_u32(sW1) + bOff };

    // prologue: unit0 = {A(tile0,r0), W6}; unit1 = {A(tile0,r1), W7}
    stage_A(sA0, nbr, is64, bid * NT, 0, N); stage_W(sW0, 6); cpa_commit();
    stage_A(sA1, nbr, is64, bid * NT, 1, N); stage_W(sW1, 7); cpa_commit();

    float acc[2][4][4];

    int k = 0, u = 0, tile = bid;
    int k2 = 0, u2 = 2, tile2 = bid;
    const int GU = 5 * K;
    for (int g = 0; g < GU; ++g) {
        cpa_wait1();
        __syncthreads();

        float C[2][4][4]; ZERO_C(C);
        gemm64m(aAb[g & 1], bAb[g & 1], C);
        __syncthreads();

        if (k2 < K) {
            stage_A(sAb[g & 1], nbr, is64, tile2 * NT, u2, N);
            stage_W(sWb[g & 1], 6 + u2);
        }
        cpa_commit();

        // epilogue: scaled accumulation
        if (u == 0) ZERO_C(acc);
        const int n0 = tile * NT;
        const float si = g_Sinv[h * 5 + u];
        float av[2][2];
        #pragma unroll
        for (int mt = 0; mt < 2; ++mt)
            #pragma unroll
            for (int rr2 = 0; rr2 < 2; ++rr2) {
                int n = n0 + wm * 32 + mt * 16 + g8 + rr2 * 8;
                av[mt][rr2] = (n < N)
                    ? __ldg(&g_E[(size_t)(h * 5 + u) * N + n]) * si : 0.f;
            }
        #pragma unroll
        for (int mt = 0; mt < 2; ++mt)
            #pragma unroll
            for (int nt = 0; nt < 4; ++nt)
                #pragma unroll
                for (int ci = 0; ci < 4; ++ci)
                    acc[mt][nt][ci] = fmaf(av[mt][ci >> 1], C[mt][nt][ci],
                                           acc[mt][nt][ci]);

        // tile end: direct STG.64 (quad = one full 32B sector)
        if (u == 4) {
            #pragma unroll
            for (int mt = 0; mt < 2; ++mt)
                #pragma unroll
                for (int rr2 = 0; rr2 < 2; ++rr2) {
                    int n = n0 + wm * 32 + mt * 16 + g8 + rr2 * 8;
                    if (n < N) {
                        #pragma unroll
                        for (int nt = 0; nt < 4; ++nt) {
                            float2 v = make_float2(acc[mt][nt][rr2 * 2],
                                                   acc[mt][nt][rr2 * 2 + 1]);
                            *(float2*)(out + (size_t)n * 128 + wn * 32 + nt * 8 + t4 * 2) = v;
                        }
                    }
                }
        }

        if (++u == 5) { u = 0; ++k; tile += grid; }
        if (++u2 == 5) { u2 = 0; ++k2; tile2 += grid; }
    }
}

extern "C" void kernel_launch(void* const* d_in, const int* in_sizes, int n_in,
                              void* d_out, int out_size)
{
    const float* x   = (const float*)d_in[0];
    const void*  nbr = d_in[1];
    const float* wq  = (const float*)d_in[2];
    const float* wk  = (const float*)d_in[3];
    const float* wv  = (const float*)d_in[4];
    float*       out = (float*)d_out;

    const int N    = in_sizes[0] / 128;
    const int NBT  = (N + NT - 1) / NT;
    const int GRID = (NBT < MAXGRID) ? NBT : MAXGRID;

    cudaFuncSetAttribute(knot_E, cudaFuncAttributeMaxDynamicSharedMemorySize, SMEM_SZ);
    cudaFuncSetAttribute(knot_O, cudaFuncAttributeMaxDynamicSharedMemorySize, SMEM_SZ);

    knot_prep_x<<<1024, 256>>>(x, (const int*)nbr, N * 128);
    knot_prep_w<<<11, 256>>>(wq, wk, wv);
    knot_E<<<GRID, THREADS, SMEM_SZ>>>(nbr, N, NBT);
    knot_R<<<20, 256>>>(16 * NBT);
    knot_O<<<GRID, THREADS, SMEM_SZ>>>(nbr, out, N, NBT);
}

// round 13
// speedup vs baseline: 1.2204x; 1.2204x over previous
#include <cuda_runtime.h>
#include <cuda_fp16.h>
#include <math.h>
#include <stdint.h>

// ===========================================================================
// KnotAttention via mma.sync m16n8k16 fp16 + ldmatrix. NT=64 tiles, 2 CTAs/SM,
// single-A + double-W cp.async pipeline (R9 skeleton), lean epilogues:
//  E: width-16 partial sums stored directly (no shfl-down/warr/extra sync)
//  O: direct STG.64 epilogue (no smem transpose)
//  Restage issued before epilogue math so copies overlap it.
// ===========================================================================

#define NT       64
#define THREADS  256
#define MAXN     131072
#define MAXTILES (MAXN / NT)
#define SCALE    0.17677669529663687f   // 1/sqrt(32)
#define SH       136                    // smem row stride in halves (272B)
#define ROWB     272
#define A_HALVES (NT * SH)              // 8704
#define W_HALVES (128 * SH)             // 17408
#define SMEM_SZ  ((A_HALVES + 2 * W_HALVES) * 2)   // 87040 B -> 2 CTAs/SM

__device__ float  g_E[(size_t)20 * MAXN];
__device__ float  g_part[20 * 16 * MAXTILES];
__device__ float  g_Sinv[20];
__device__ int    g_is64;
__device__ __half g_Wh[11 * 128 * 128];          // [slot][n][k]
__device__ __half g_xh[(size_t)MAXN * 128];      // [n][k]

// -------- helpers --------
__device__ __forceinline__ uint32_t smem_u32(const void* p) {
    uint32_t a;
    asm("{ .reg .u64 t; cvta.to.shared.u64 t, %1; cvt.u32.u64 %0, t; }" : "=r"(a) : "l"(p));
    return a;
}
__device__ __forceinline__ void cpa16(uint32_t s, const void* g) {
    asm volatile("cp.async.cg.shared.global [%0], [%1], 16;" :: "r"(s), "l"(g) : "memory");
}
__device__ __forceinline__ void cpa_commit() { asm volatile("cp.async.commit_group;" ::: "memory"); }
__device__ __forceinline__ void cpa_wait1()  { asm volatile("cp.async.wait_group 1;" ::: "memory"); }
__device__ __forceinline__ void cpa_wait0()  { asm volatile("cp.async.wait_group 0;" ::: "memory"); }

__device__ __forceinline__ void ldsm4(uint32_t& r0, uint32_t& r1, uint32_t& r2,
                                      uint32_t& r3, uint32_t addr) {
    asm volatile("ldmatrix.sync.aligned.m8n8.x4.shared.b16 {%0,%1,%2,%3}, [%4];"
                 : "=r"(r0), "=r"(r1), "=r"(r2), "=r"(r3) : "r"(addr));
}
__device__ __forceinline__ void mma16816(float* c, uint32_t a0, uint32_t a1,
                                         uint32_t a2, uint32_t a3,
                                         uint32_t b0, uint32_t b1) {
    asm volatile(
        "mma.sync.aligned.m16n8k16.row.col.f32.f16.f16.f32 "
        "{%0,%1,%2,%3}, {%4,%5,%6,%7}, {%8,%9}, {%0,%1,%2,%3};"
        : "+f"(c[0]), "+f"(c[1]), "+f"(c[2]), "+f"(c[3])
        : "r"(a0), "r"(a1), "r"(a2), "r"(a3), "r"(b0), "r"(b1));
}

// -------- prep kernels --------
__global__ void knot_prep_x(const float* __restrict__ x,
                            const int* __restrict__ nbr_i32, int total4)
{
    if (blockIdx.x == 0 && threadIdx.x == 0) {
        int any = 0;
        #pragma unroll
        for (int i = 1; i < 64; i += 2) any |= nbr_i32[i];
        g_is64 = (any == 0) ? 1 : 0;
    }
    for (int i = blockIdx.x * 256 + threadIdx.x; i < total4; i += gridDim.x * 256) {
        float4 v = __ldg((const float4*)x + i);
        __half2* d = (__half2*)(g_xh + (size_t)i * 4);
        d[0] = __floats2half2_rn(v.x, v.y);
        d[1] = __floats2half2_rn(v.z, v.w);
    }
}
__global__ void knot_prep_w(const float* __restrict__ wq, const float* __restrict__ wk,
                            const float* __restrict__ wv)
{
    int slot = blockIdx.x;
    __half* dst = g_Wh + slot * 16384;
    for (int i = 0; i < 64; ++i) {
        int f = threadIdx.x + 256 * i;
        int n = f >> 7, d = f & 127;
        int h = n >> 5, k = n & 31;
        float v;
        if (slot == 0)      v = wq[((size_t)h * 128 + d) * 32 + k];
        else if (slot <= 5) v = wk[(((size_t)(h * 5 + (slot - 1)) * 128) + d) * 32 + k];
        else                v = wv[(((size_t)(h * 5 + (slot - 6)) * 128) + d) * 32 + k];
        dst[n * 128 + d] = __float2half_rn(v);
    }
}

// -------- staging (cp.async 16B) --------
__device__ __forceinline__ void stage_A(__half* sA, const void* __restrict__ nbr,
                                        int is64, int n0, int r, int N)
{
    int t = threadIdx.x;
    #pragma unroll
    for (int i = 0; i < 4; ++i) {
        int f = t + 256 * i;               // 64 rows x 16 chunks of 16B
        int row = f >> 4, c16 = f & 15;
        int n = n0 + row;
        int nc = (n < N) ? n : 0;
        long long src;
        if (r == 0) src = nc;
        else {
            long long e = (long long)nc * 4 + (r - 1);
            src = is64 ? __ldg((const long long*)nbr + e)
                       : (long long)__ldg((const int*)nbr + e);
        }
        if (src < 0) src = 0;
        if (src >= N) src = N - 1;
        cpa16(smem_u32(sA + row * SH + c16 * 8), g_xh + ((size_t)src << 7) + c16 * 8);
    }
}
__device__ __forceinline__ void stage_W(__half* sW, int slot)
{
    const __half* src = g_Wh + slot * 16384;
    int t = threadIdx.x;
    #pragma unroll
    for (int i = 0; i < 8; ++i) {
        int f = t + 256 * i;
        int row = f >> 4, c16 = f & 15;
        cpa16(smem_u32(sW + row * SH + c16 * 8), src + row * 128 + c16 * 8);
    }
}

// -------- warp GEMM via ldmatrix: 32(m) x 32(n) per warp --------
__device__ __forceinline__ void gemm64m(uint32_t aAddr, uint32_t bAddr,
                                        float C[2][4][4])
{
    #pragma unroll
    for (int ks = 0; ks < 8; ++ks) {
        uint32_t a0[4], a1[4], b0[4], b1[4];
        ldsm4(a0[0], a0[1], a0[2], a0[3], aAddr + ks * 32);
        ldsm4(a1[0], a1[1], a1[2], a1[3], aAddr + 16 * ROWB + ks * 32);
        ldsm4(b0[0], b0[1], b0[2], b0[3], bAddr + ks * 32);
        ldsm4(b1[0], b1[1], b1[2], b1[3], bAddr + 16 * ROWB + ks * 32);
        mma16816(C[0][0], a0[0], a0[1], a0[2], a0[3], b0[0], b0[1]);
        mma16816(C[0][1], a0[0], a0[1], a0[2], a0[3], b0[2], b0[3]);
        mma16816(C[0][2], a0[0], a0[1], a0[2], a0[3], b1[0], b1[1]);
        mma16816(C[0][3], a0[0], a0[1], a0[2], a0[3], b1[2], b1[3]);
        mma16816(C[1][0], a1[0], a1[1], a1[2], a1[3], b0[0], b0[1]);
        mma16816(C[1][1], a1[0], a1[1], a1[2], a1[3], b0[2], b0[3]);
        mma16816(C[1][2], a1[0], a1[1], a1[2], a1[3], b1[0], b1[1]);
        mma16816(C[1][3], a1[0], a1[1], a1[2], a1[3], b1[2], b1[3]);
    }
}

#define ZERO_C(C)                                                   \
    _Pragma("unroll") for (int mt = 0; mt < 2; ++mt)                \
    _Pragma("unroll") for (int nt = 0; nt < 4; ++nt)                \
    _Pragma("unroll") for (int ci = 0; ci < 4; ++ci) C[mt][nt][ci] = 0.f;

// -------- kernel E --------
__global__ __launch_bounds__(THREADS, 2)
void knot_E(const void* __restrict__ nbr, int N)
{
    extern __shared__ __align__(16) char smc[];
    __half* sA  = (__half*)smc;
    __half* sW0 = sA + A_HALVES;
    __half* sW1 = sW0 + W_HALVES;

    const int t = threadIdx.x, w = t >> 5, l = t & 31;
    const int wm = w >> 2, wn = w & 3, g8 = l >> 2, t4 = l & 3;
    const int tile = blockIdx.x, n0 = tile * NT;
    const int is64 = g_is64;
    const int h = wn;

    const int j = l >> 3, lr = l & 7;
    const uint32_t aAddr = smem_u32(sA) + (wm * 32 + (j & 1) * 8 + lr) * ROWB + (j >> 1) * 16;
    const uint32_t bOff  = (wn * 32 + (j >> 1) * 8 + lr) * ROWB + (j & 1) * 16;
    const uint32_t bAb[2] = { smem_u32(sW0) + bOff, smem_u32(sW1) + bOff };

    // prologue: g1={W0}, g2={A0}, g3={W1}
    stage_W(sW0, 0); cpa_commit();
    stage_A(sA, nbr, is64, n0, 0, N); cpa_commit();
    stage_W(sW1, 1); cpa_commit();

    // ---- Q (buf0) ----
    float qC[2][4][4]; ZERO_C(qC);
    cpa_wait1();
    __syncthreads();
    gemm64m(aAddr, bAb[0], qC);
    __syncthreads();
    stage_W(sW0, 2); cpa_commit();        // g4={W2}

    for (int r = 0; r < 5; ++r) {
        if (r < 4) cpa_wait1(); else cpa_wait0();
        __syncthreads();

        float kC[2][4][4]; ZERO_C(kC);
        gemm64m(aAddr, bAb[(r + 1) & 1], kC);
        __syncthreads();                  // GEMM smem reads done

        // restage FIRST so copies overlap epilogue math
        if (r + 1 < 5)  { stage_A(sA, nbr, is64, n0, r + 1, N); cpa_commit(); }
        if (r + 3 <= 5) { stage_W((r + 1) & 1 ? sW1 : sW0, r + 3); cpa_commit(); }

        // ---- epilogue: logits, exp, E store, width-16 partials ----
        float hs = 0.f;
        #pragma unroll
        for (int mt = 0; mt < 2; ++mt) {
            #pragma unroll
            for (int rr2 = 0; rr2 < 2; ++rr2) {
                int n = n0 + wm * 32 + mt * 16 + g8 + rr2 * 8;
                float ds = 0.f;
                #pragma unroll
                for (int nt = 0; nt < 4; ++nt) {
                    ds = fmaf(qC[mt][nt][rr2 * 2],     kC[mt][nt][rr2 * 2],     ds);
                    ds = fmaf(qC[mt][nt][rr2 * 2 + 1], kC[mt][nt][rr2 * 2 + 1], ds);
                }
                ds += __shfl_xor_sync(0xFFFFFFFFu, ds, 1);
                ds += __shfl_xor_sync(0xFFFFFFFFu, ds, 2);
                if (t4 == 0) {
                    float e = 0.f;
                    if (n < N) {
                        e = __expf(ds * SCALE);
                        g_E[(size_t)(h * 5 + r) * N + n] = e;
                    }
                    hs += e;
                }
            }
        }
        if (t4 == 0)
            g_part[(size_t)(h * 5 + r) * (16 * MAXTILES) + tile * 16 + wm * 8 + g8] = hs;
    }
}

// -------- kernel R --------
__global__ void knot_R(int cnt)
{
    __shared__ float smr[256];
    const int b = blockIdx.x;
    float s = 0.f;
    for (int i = threadIdx.x; i < cnt; i += 256)
        s += g_part[(size_t)b * (16 * MAXTILES) + i];
    smr[threadIdx.x] = s;
    __syncthreads();
    for (int off = 128; off > 0; off >>= 1) {
        if (threadIdx.x < off) smr[threadIdx.x] += smr[threadIdx.x + off];
        __syncthreads();
    }
    if (threadIdx.x == 0) g_Sinv[b] = 1.0f / smr[0];
}

// -------- kernel O --------
__global__ __launch_bounds__(THREADS, 2)
void knot_O(const void* __restrict__ nbr, float* __restrict__ out, int N)
{
    extern __shared__ __align__(16) char smc[];
    __half* sA  = (__half*)smc;
    __half* sW0 = sA + A_HALVES;
    __half* sW1 = sW0 + W_HALVES;

    const int t = threadIdx.x, w = t >> 5, l = t & 31;
    const int wm = w >> 2, wn = w & 3, g8 = l >> 2, t4 = l & 3;
    const int tile = blockIdx.x, n0 = tile * NT;
    const int is64 = g_is64;
    const int h = wn;

    const int j = l >> 3, lr = l & 7;
    const uint32_t aAddr = smem_u32(sA) + (wm * 32 + (j & 1) * 8 + lr) * ROWB + (j >> 1) * 16;
    const uint32_t bOff  = (wn * 32 + (j >> 1) * 8 + lr) * ROWB + (j & 1) * 16;
    const uint32_t bAb[2] = { smem_u32(sW0) + bOff, smem_u32(sW1) + bOff };

    // prologue: g1={W6}, g2={A0}, g3={W7}
    stage_W(sW0, 6); cpa_commit();
    stage_A(sA, nbr, is64, n0, 0, N); cpa_commit();
    stage_W(sW1, 7); cpa_commit();

    float acc[2][4][4]; ZERO_C(acc);

    for (int r = 0; r < 5; ++r) {
        if (r < 4) cpa_wait1(); else cpa_wait0();
        __syncthreads();

        float C[2][4][4]; ZERO_C(C);
        gemm64m(aAddr, bAb[r & 1], C);
        __syncthreads();                  // GEMM smem reads done

        // restage FIRST
        if (r + 1 <= 4) { stage_A(sA, nbr, is64, n0, r + 1, N); cpa_commit(); }
        if (r + 2 <= 4) { stage_W(r & 1 ? sW1 : sW0, 6 + r + 2); cpa_commit(); }

        // ---- epilogue: scaled accumulation ----
        float av[2][2];
        const float si = g_Sinv[h * 5 + r];
        #pragma unroll
        for (int mt = 0; mt < 2; ++mt)
            #pragma unroll
            for (int rr2 = 0; rr2 < 2; ++rr2) {
                int n = n0 + wm * 32 + mt * 16 + g8 + rr2 * 8;
                av[mt][rr2] = (n < N)
                    ? __ldg(&g_E[(size_t)(h * 5 + r) * N + n]) * si : 0.f;
            }
        #pragma unroll
        for (int mt = 0; mt < 2; ++mt)
            #pragma unroll
            for (int nt = 0; nt < 4; ++nt)
                #pragma unroll
                for (int ci = 0; ci < 4; ++ci)
                    acc[mt][nt][ci] = fmaf(av[mt][ci >> 1], C[mt][nt][ci],
                                           acc[mt][nt][ci]);
    }

    // ---- direct STG epilogue (quad covers a full 32B sector per row) ----
    #pragma unroll
    for (int mt = 0; mt < 2; ++mt)
        #pragma unroll
        for (int rr2 = 0; rr2 < 2; ++rr2) {
            int n = n0 + wm * 32 + mt * 16 + g8 + rr2 * 8;
            if (n < N) {
                #pragma unroll
                for (int nt = 0; nt < 4; ++nt) {
                    float2 v = make_float2(acc[mt][nt][rr2 * 2],
                                           acc[mt][nt][rr2 * 2 + 1]);
                    *(float2*)(out + (size_t)n * 128 + wn * 32 + nt * 8 + t4 * 2) = v;
                }
            }
        }
}

extern "C" void kernel_launch(void* const* d_in, const int* in_sizes, int n_in,
                              void* d_out, int out_size)
{
    const float* x   = (const float*)d_in[0];
    const void*  nbr = d_in[1];
    const float* wq  = (const float*)d_in[2];
    const float* wk  = (const float*)d_in[3];
    const float* wv  = (const float*)d_in[4];
    float*       out = (float*)d_out;

    const int N   = in_sizes[0] / 128;
    const int NBT = (N + NT - 1) / NT;

    cudaFuncSetAttribute(knot_E, cudaFuncAttributeMaxDynamicSharedMemorySize, SMEM_SZ);
    cudaFuncSetAttribute(knot_O, cudaFuncAttributeMaxDynamicSharedMemorySize, SMEM_SZ);

    knot_prep_x<<<1024, 256>>>(x, (const int*)nbr, N * 32);
    knot_prep_w<<<11, 256>>>(wq, wk, wv);
    knot_E<<<NBT, THREADS, SMEM_SZ>>>(nbr, N);
    knot_R<<<20, 256>>>(16 * NBT);
    knot_O<<<NBT, THREADS, SMEM_SZ>>>(nbr, out, N);
}

// round 17
// speedup vs baseline: 1.2441x; 1.0194x over previous
#include <cuda_runtime.h>
#include <cuda_fp16.h>
#include <math.h>
#include <stdint.h>

// ===========================================================================
// KnotAttention via mma.sync m16n8k16 fp16 + ldmatrix. NT=64 tiles, 2 CTAs/SM.
// ONE barrier per GEMM unit: top sync proves prior iteration's smem reads are
// done, so next-unit staging issues right after it and overlaps the GEMM.
//  E: per tile: Q, K_0..4 -> exp(logits), width-16 partials
//  R: reduce partials -> 1/denominator (softmax over NODE axis), 1024-thr blocks
//  O: per tile: V_0..4 -> acc += (E*Sinv)*V_r -> direct STG
// ===========================================================================

#define NT       64
#define THREADS  256
#define MAXN     131072
#define MAXTILES (MAXN / NT)
#define SCALE    0.17677669529663687f   // 1/sqrt(32)
#define SH       136                    // smem row stride in halves (272B)
#define ROWB     272
#define A_HALVES (NT * SH)              // 8704
#define W_HALVES (128 * SH)             // 17408
#define SMEM_SZ  ((2 * A_HALVES + 2 * W_HALVES) * 2)   // 104448 B -> 2 CTAs/SM

__device__ float  g_E[(size_t)20 * MAXN];
__device__ float  g_part[20 * 16 * MAXTILES];
__device__ float  g_Sinv[20];
__device__ int    g_is64;
__device__ __half g_Wh[11 * 128 * 128];          // [slot][n][k]
__device__ __half g_xh[(size_t)MAXN * 128];      // [n][k]

// -------- helpers --------
__device__ __forceinline__ uint32_t smem_u32(const void* p) {
    uint32_t a;
    asm("{ .reg .u64 t; cvta.to.shared.u64 t, %1; cvt.u32.u64 %0, t; }" : "=r"(a) : "l"(p));
    return a;
}
__device__ __forceinline__ void cpa16(uint32_t s, const void* g) {
    asm volatile("cp.async.cg.shared.global [%0], [%1], 16;" :: "r"(s), "l"(g) : "memory");
}
__device__ __forceinline__ void cpa_commit() { asm volatile("cp.async.commit_group;" ::: "memory"); }
__device__ __forceinline__ void cpa_wait0()  { asm volatile("cp.async.wait_group 0;" ::: "memory"); }

__device__ __forceinline__ void ldsm4(uint32_t& r0, uint32_t& r1, uint32_t& r2,
                                      uint32_t& r3, uint32_t addr) {
    asm volatile("ldmatrix.sync.aligned.m8n8.x4.shared.b16 {%0,%1,%2,%3}, [%4];"
                 : "=r"(r0), "=r"(r1), "=r"(r2), "=r"(r3) : "r"(addr));
}
__device__ __forceinline__ void mma16816(float* c, uint32_t a0, uint32_t a1,
                                         uint32_t a2, uint32_t a3,
                                         uint32_t b0, uint32_t b1) {
    asm volatile(
        "mma.sync.aligned.m16n8k16.row.col.f32.f16.f16.f32 "
        "{%0,%1,%2,%3}, {%4,%5,%6,%7}, {%8,%9}, {%0,%1,%2,%3};"
        : "+f"(c[0]), "+f"(c[1]), "+f"(c[2]), "+f"(c[3])
        : "r"(a0), "r"(a1), "r"(a2), "r"(a3), "r"(b0), "r"(b1));
}

// -------- prep kernels --------
__global__ void knot_prep_x(const float* __restrict__ x,
                            const int* __restrict__ nbr_i32, int total4)
{
    if (blockIdx.x == 0 && threadIdx.x == 0) {
        int any = 0;
        #pragma unroll
        for (int i = 1; i < 64; i += 2) any |= nbr_i32[i];
        g_is64 = (any == 0) ? 1 : 0;
    }
    for (int i = blockIdx.x * 256 + threadIdx.x; i < total4; i += gridDim.x * 256) {
        float4 v = __ldg((const float4*)x + i);
        __half2* d = (__half2*)(g_xh + (size_t)i * 4);
        d[0] = __floats2half2_rn(v.x, v.y);
        d[1] = __floats2half2_rn(v.z, v.w);
    }
}
__global__ void knot_prep_w(const float* __restrict__ wq, const float* __restrict__ wk,
                            const float* __restrict__ wv)
{
    int slot = blockIdx.x;
    __half* dst = g_Wh + slot * 16384;
    for (int i = 0; i < 64; ++i) {
        int f = threadIdx.x + 256 * i;
        int n = f >> 7, d = f & 127;
        int h = n >> 5, k = n & 31;
        float v;
        if (slot == 0)      v = wq[((size_t)h * 128 + d) * 32 + k];
        else if (slot <= 5) v = wk[(((size_t)(h * 5 + (slot - 1)) * 128) + d) * 32 + k];
        else                v = wv[(((size_t)(h * 5 + (slot - 6)) * 128) + d) * 32 + k];
        dst[n * 128 + d] = __float2half_rn(v);
    }
}

// -------- staging (cp.async 16B) --------
__device__ __forceinline__ void stage_A(__half* sA, const void* __restrict__ nbr,
                                        int is64, int n0, int r, int N)
{
    int t = threadIdx.x;
    #pragma unroll
    for (int i = 0; i < 4; ++i) {
        int f = t + 256 * i;               // 64 rows x 16 chunks of 16B
        int row = f >> 4, c16 = f & 15;
        int n = n0 + row;
        int nc = (n < N) ? n : 0;
        long long src;
        if (r == 0) src = nc;
        else {
            long long e = (long long)nc * 4 + (r - 1);
            src = is64 ? __ldg((const long long*)nbr + e)
                       : (long long)__ldg((const int*)nbr + e);
        }
        if (src < 0) src = 0;
        if (src >= N) src = N - 1;
        cpa16(smem_u32(sA + row * SH + c16 * 8), g_xh + ((size_t)src << 7) + c16 * 8);
    }
}
__device__ __forceinline__ void stage_W(__half* sW, int slot)
{
    const __half* src = g_Wh + slot * 16384;
    int t = threadIdx.x;
    #pragma unroll
    for (int i = 0; i < 8; ++i) {
        int f = t + 256 * i;
        int row = f >> 4, c16 = f & 15;
        cpa16(smem_u32(sW + row * SH + c16 * 8), src + row * 128 + c16 * 8);
    }
}

// -------- warp GEMM via ldmatrix: 32(m) x 32(n) per warp --------
__device__ __forceinline__ void gemm64m(uint32_t aAddr, uint32_t bAddr,
                                        float C[2][4][4])
{
    #pragma unroll
    for (int ks = 0; ks < 8; ++ks) {
        uint32_t a0[4], a1[4], b0[4], b1[4];
        ldsm4(a0[0], a0[1], a0[2], a0[3], aAddr + ks * 32);
        ldsm4(a1[0], a1[1], a1[2], a1[3], aAddr + 16 * ROWB + ks * 32);
        ldsm4(b0[0], b0[1], b0[2], b0[3], bAddr + ks * 32);
        ldsm4(b1[0], b1[1], b1[2], b1[3], bAddr + 16 * ROWB + ks * 32);
        mma16816(C[0][0], a0[0], a0[1], a0[2], a0[3], b0[0], b0[1]);
        mma16816(C[0][1], a0[0], a0[1], a0[2], a0[3], b0[2], b0[3]);
        mma16816(C[0][2], a0[0], a0[1], a0[2], a0[3], b1[0], b1[1]);
        mma16816(C[0][3], a0[0], a0[1], a0[2], a0[3], b1[2], b1[3]);
        mma16816(C[1][0], a1[0], a1[1], a1[2], a1[3], b0[0], b0[1]);
        mma16816(C[1][1], a1[0], a1[1], a1[2], a1[3], b0[2], b0[3]);
        mma16816(C[1][2], a1[0], a1[1], a1[2], a1[3], b1[0], b1[1]);
        mma16816(C[1][3], a1[0], a1[1], a1[2], a1[3], b1[2], b1[3]);
    }
}

#define ZERO_C(C)                                                   \
    _Pragma("unroll") for (int mt = 0; mt < 2; ++mt)                \
    _Pragma("unroll") for (int nt = 0; nt < 4; ++nt)                \
    _Pragma("unroll") for (int ci = 0; ci < 4; ++ci) C[mt][nt][ci] = 0.f;

// ---------------- kernel E ----------------
// Units i=0..5: i=0 Q=(A0,W0); i>=1 K_{i-1}=(A_{i-1}, W_i).
// A_k lives in aslot k&1; W_i in wslot i&1. Stage for unit i+1 at top of i.
__global__ __launch_bounds__(THREADS, 2)
void knot_E(const void* __restrict__ nbr, int N)
{
    extern __shared__ __align__(16) char smc[];
    __half* sA0 = (__half*)smc;
    __half* sA1 = sA0 + A_HALVES;
    __half* sW0 = sA1 + A_HALVES;
    __half* sW1 = sW0 + W_HALVES;
    __half* sAb[2] = { sA0, sA1 };
    __half* sWb[2] = { sW0, sW1 };

    const int t = threadIdx.x, w = t >> 5, l = t & 31;
    const int wm = w >> 2, wn = w & 3, g8 = l >> 2, t4 = l & 3;
    const int tile = blockIdx.x, n0 = tile * NT;
    const int is64 = g_is64;
    const int h = wn;

    const int j = l >> 3, lr = l & 7;
    const uint32_t aOff = (wm * 32 + (j & 1) * 8 + lr) * ROWB + (j >> 1) * 16;
    const uint32_t bOff = (wn * 32 + (j >> 1) * 8 + lr) * ROWB + (j & 1) * 16;
    const uint32_t aAb[2] = { smem_u32(sA0) + aOff, smem_u32(sA1) + aOff };
    const uint32_t bAb[2] = { smem_u32(sW0) + bOff, smem_u32(sW1) + bOff };

    // prologue: unit 0 operands {W0, A0}
    stage_W(sW0, 0); stage_A(sA0, nbr, is64, n0, 0, N); cpa_commit();

    float qC[2][4][4], kC[2][4][4];

    #pragma unroll
    for (int i = 0; i < 6; ++i) {
        cpa_wait0();
        __syncthreads();                   // prior iter's smem reads done

        // stage unit i+1 operands (slots (i+1)&1; last read at unit i-1)
        if (i < 5) {
            stage_W(sWb[(i + 1) & 1], i + 1);
            if (i >= 1) stage_A(sAb[i & 1], nbr, is64, n0, i, N);  // A_i
            cpa_commit();
        }

        if (i == 0) {
            ZERO_C(qC);
            gemm64m(aAb[0], bAb[0], qC);
        } else {
            ZERO_C(kC);
            gemm64m(aAb[(i - 1) & 1], bAb[i & 1], kC);

            // ---- epilogue r = i-1: logits, exp, E store, width-16 partials ----
            const int r = i - 1;
            float hs = 0.f;
            #pragma unroll
            for (int mt = 0; mt < 2; ++mt) {
                #pragma unroll
                for (int rr2 = 0; rr2 < 2; ++rr2) {
                    int n = n0 + wm * 32 + mt * 16 + g8 + rr2 * 8;
                    float ds = 0.f;
                    #pragma unroll
                    for (int nt = 0; nt < 4; ++nt) {
                        ds = fmaf(qC[mt][nt][rr2 * 2],     kC[mt][nt][rr2 * 2],     ds);
                        ds = fmaf(qC[mt][nt][rr2 * 2 + 1], kC[mt][nt][rr2 * 2 + 1], ds);
                    }
                    ds += __shfl_xor_sync(0xFFFFFFFFu, ds, 1);
                    ds += __shfl_xor_sync(0xFFFFFFFFu, ds, 2);
                    if (t4 == 0) {
                        float e = 0.f;
                        if (n < N) {
                            e = __expf(ds * SCALE);
                            g_E[(size_t)(h * 5 + r) * N + n] = e;
                        }
                        hs += e;
                    }
                }
            }
            if (t4 == 0)
                g_part[(size_t)(h * 5 + r) * (16 * MAXTILES) + tile * 16 + wm * 8 + g8] = hs;
        }
    }
}

// ---------------- kernel R (1024-thread blocks, float4 loads) ----------------
__global__ void knot_R(int cnt4)
{
    __shared__ float smr[1024];
    const int b = blockIdx.x;
    const float4* src = (const float4*)(g_part + (size_t)b * (16 * MAXTILES));
    float s = 0.f;
    for (int i = threadIdx.x; i < cnt4; i += 1024) {
        float4 v = __ldg(src + i);
        s += (v.x + v.y) + (v.z + v.w);
    }
    smr[threadIdx.x] = s;
    __syncthreads();
    for (int off = 512; off > 0; off >>= 1) {
        if (threadIdx.x < off) smr[threadIdx.x] += smr[threadIdx.x + off];
        __syncthreads();
    }
    if (threadIdx.x == 0) g_Sinv[b] = 1.0f / smr[0];
}

// ---------------- kernel O ----------------
// Units r=0..4: V_r = (A_r, W_{6+r}); aslot/wslot = r&1. Stage r+1 at top of r.
__global__ __launch_bounds__(THREADS, 2)
void knot_O(const void* __restrict__ nbr, float* __restrict__ out, int N)
{
    extern __shared__ __align__(16) char smc[];
    __half* sA0 = (__half*)smc;
    __half* sA1 = sA0 + A_HALVES;
    __half* sW0 = sA1 + A_HALVES;
    __half* sW1 = sW0 + W_HALVES;
    __half* sAb[2] = { sA0, sA1 };
    __half* sWb[2] = { sW0, sW1 };

    const int t = threadIdx.x, w = t >> 5, l = t & 31;
    const int wm = w >> 2, wn = w & 3, g8 = l >> 2, t4 = l & 3;
    const int tile = blockIdx.x, n0 = tile * NT;
    const int is64 = g_is64;
    const int h = wn;

    const int j = l >> 3, lr = l & 7;
    const uint32_t aOff = (wm * 32 + (j & 1) * 8 + lr) * ROWB + (j >> 1) * 16;
    const uint32_t bOff = (wn * 32 + (j >> 1) * 8 + lr) * ROWB + (j & 1) * 16;
    const uint32_t aAb[2] = { smem_u32(sA0) + aOff, smem_u32(sA1) + aOff };
    const uint32_t bAb[2] = { smem_u32(sW0) + bOff, smem_u32(sW1) + bOff };

    // prologue: unit 0 operands {A0, W6}
    stage_A(sA0, nbr, is64, n0, 0, N); stage_W(sW0, 6); cpa_commit();

    float acc[2][4][4]; ZERO_C(acc);

    #pragma unroll
    for (int r = 0; r < 5; ++r) {
        cpa_wait0();
        __syncthreads();                   // prior iter's smem reads done

        if (r < 4) {
            stage_A(sAb[(r + 1) & 1], nbr, is64, n0, r + 1, N);
            stage_W(sWb[(r + 1) & 1], 7 + r);
            cpa_commit();
        }

        float C[2][4][4]; ZERO_C(C);
        gemm64m(aAb[r & 1], bAb[r & 1], C);

        // ---- epilogue: scaled accumulation ----
        float av[2][2];
        const float si = g_Sinv[h * 5 + r];
        #pragma unroll
        for (int mt = 0; mt < 2; ++mt)
            #pragma unroll
            for (int rr2 = 0; rr2 < 2; ++rr2) {
                int n = n0 + wm * 32 + mt * 16 + g8 + rr2 * 8;
                av[mt][rr2] = (n < N)
                    ? __ldg(&g_E[(size_t)(h * 5 + r) * N + n]) * si : 0.f;
            }
        #pragma unroll
        for (int mt = 0; mt < 2; ++mt)
            #pragma unroll
            for (int nt = 0; nt < 4; ++nt)
                #pragma unroll
                for (int ci = 0; ci < 4; ++ci)
                    acc[mt][nt][ci] = fmaf(av[mt][ci >> 1], C[mt][nt][ci],
                                           acc[mt][nt][ci]);
    }

    // ---- direct STG epilogue (quad covers a full 32B sector per row) ----
    #pragma unroll
    for (int mt = 0; mt < 2; ++mt)
        #pragma unroll
        for (int rr2 = 0; rr2 < 2; ++rr2) {
            int n = n0 + wm * 32 + mt * 16 + g8 + rr2 * 8;
            if (n < N) {
                #pragma unroll
                for (int nt = 0; nt < 4; ++nt) {
                    float2 v = make_float2(acc[mt][nt][rr2 * 2],
                                           acc[mt][nt][rr2 * 2 + 1]);
                    *(float2*)(out + (size_t)n * 128 + wn * 32 + nt * 8 + t4 * 2) = v;
                }
            }
        }
}

extern "C" void kernel_launch(void* const* d_in, const int* in_sizes, int n_in,
                              void* d_out, int out_size)
{
    const float* x   = (const float*)d_in[0];
    const void*  nbr = d_in[1];
    const float* wq  = (const float*)d_in[2];
    const float* wk  = (const float*)d_in[3];
    const float* wv  = (const float*)d_in[4];
    float*       out = (float*)d_out;

    const int N   = in_sizes[0] / 128;
    const int NBT = (N + NT - 1) / NT;

    cudaFuncSetAttribute(knot_E, cudaFuncAttributeMaxDynamicSharedMemorySize, SMEM_SZ);
    cudaFuncSetAttribute(knot_O, cudaFuncAttributeMaxDynamicSharedMemorySize, SMEM_SZ);

    knot_prep_x<<<1024, 256>>>(x, (const int*)nbr, N * 32);
    knot_prep_w<<<11, 256>>>(wq, wk, wv);
    knot_E<<<NBT, THREADS, SMEM_SZ>>>(nbr, N);
    knot_R<<<20, 1024>>>(16 * NBT / 4);
    knot_O<<<NBT, THREADS, SMEM_SZ>>>(nbr, out, N);
}